// round 12
// baseline (speedup 1.0000x reference)
#include <cuda_runtime.h>
#include <math.h>

// Problem constants
#define BB 2048   // batch
#define DD 512    // hidden
#define CC 128    // vocab
#define TT 151    // steps
#define G3 1536   // 3*DD

// Persistent scratch (allowed: __device__ globals, no runtime allocation)
__device__ float g_h[2][BB * DD];             // ping-pong hidden state [m][k], 8 MB
__device__ float g_hT[2][DD * BB];            // ping-pong hidden state [k][m], 8 MB
__device__ float g_tab[(CC + 1) * G3];        // gi table: embed@W_ih^T + b_ih (+ b_hh r/z folded)
__device__ int   g_tok[BB];                   // previous token per batch row
__device__ float g_log[(size_t)BB * TT * CC]; // logits staged [B,T,C] (coalesced), 158 MB
__device__ float g_part[16 * BB * CC];        // projection partials [n_tile][B][C], 16 MB
__device__ float g_wpt[DD * CC];              // W_proj transposed [D][C], 256 KB
__device__ float g_whhT[DD * G3];             // W_hh transposed [k][3D], 3 MB

__device__ __forceinline__ float sigm(float x) { return 1.f / (1.f + expf(-x)); }

// Packed fp32x2 FMA (Blackwell FFMA2; only reachable via PTX fma.rn.f32x2)
#define FMA2(acc, a, b) \
    asm("fma.rn.f32x2 %0, %1, %2, %0;" : "+l"(acc) : "l"(a), "l"(b))

__device__ __forceinline__ float lo32(unsigned long long v) { return __uint_as_float((unsigned)v); }
__device__ __forceinline__ float hi32(unsigned long long v) { return __uint_as_float((unsigned)(v >> 32)); }

// ---------------------------------------------------------------------------
// Precompute gi table: g_tab[c][j] = embed[c]·W_ih[j] + b_ih[j] + (j<1024 ? b_hh[j] : 0)
// Row CC (=128) is the zero-input row (t=0): just the biases.
// ---------------------------------------------------------------------------
__global__ void build_tab(const float* __restrict__ Wih, const float* __restrict__ bih,
                          const float* __restrict__ bhh, const float* __restrict__ embed) {
    __shared__ float se[DD];
    int c = blockIdx.x;                      // 0..128
    int j = blockIdx.y * 256 + threadIdx.x;  // 0..1535
    for (int i = threadIdx.x; i < DD; i += 256)
        se[i] = (c < CC) ? embed[c * DD + i] : 0.f;
    __syncthreads();
    float acc = bih[j] + (j < 2 * DD ? bhh[j] : 0.f);
    if (c < CC) {
        const float4* w  = (const float4*)(Wih + (size_t)j * DD);
        const float4* s4 = (const float4*)se;
        #pragma unroll 8
        for (int k = 0; k < DD / 4; k++) {
            float4 wv = w[k], sv = s4[k];
            acc += wv.x * sv.x;
            acc += wv.y * sv.y;
            acc += wv.z * sv.z;
            acc += wv.w * sv.w;
        }
    }
    g_tab[(size_t)c * G3 + j] = acc;
}

// W_proj^T: g_wpt[n][c] = Wp[c][n]  (one-time, coalesced writes)
__global__ void build_wpt(const float* __restrict__ Wp) {
    int i = blockIdx.x * 256 + threadIdx.x;  // 0 .. 512*128-1
    int n = i >> 7, c = i & 127;
    g_wpt[n * CC + c] = Wp[(size_t)c * DD + n];
}

// W_hh^T: g_whhT[k*1536 + j] = Whh[j*512 + k]  (one-time)
__global__ void build_whhT(const float* __restrict__ Whh) {
    int i = blockIdx.x * 256 + threadIdx.x;  // over 512*1536
    int k = i / G3, j = i - k * G3;
    g_whhT[i] = Whh[(size_t)j * DD + k];
}

// feat^T into g_hT[1] (the "previous" buffer for t=0)
__global__ void build_featT(const float* __restrict__ feat) {
    int i = blockIdx.x * 256 + threadIdx.x;  // over 512*2048
    int k = i >> 11, m = i & 2047;
    g_hT[1][i] = feat[(size_t)m * DD + k];
}

__global__ void init_tok() {
    int i = blockIdx.x * blockDim.x + threadIdx.x;
    if (i < BB) g_tok[i] = CC;  // zero-input table row
}

// ---------------------------------------------------------------------------
// Kernel 1: gh = h @ W_hh^T, fused gates + gi table lookup -> h_new (+h_T),
//           PLUS this CTA's 32-col partial of the projection h_new @ Wp^T.
// grid (BB/64, DD/32) = (32, 16) = 512 CTAs, 256 threads, occ 4.
// Per-thread 4m x 2n x 3 gates; A and B staged via pre-transposed layouts
// (pure coalesced LDG.128 -> STS.128, no in-kernel transpose).
// ---------------------------------------------------------------------------
__global__ __launch_bounds__(256, 4)
void step_h(const float* __restrict__ feat, const float* __restrict__ bhh, int t) {
    // Smem union:
    //   GEMM phase: As[2][16][66] float2 (16896 B) + Bs[2][3][16][36] float (13824 B)
    //   Proj phase: Hs[64][36] float (9216 B) overlapping As
    __shared__ __align__(16) unsigned char sraw[30720];
    float2 (*As)[16][66]    = (float2(*)[16][66])sraw;
    float  (*Bs)[3][16][36] = (float(*)[3][16][36])(sraw + 16896);
    float* Hs = (float*)sraw;  // stride 36

    const float* hTprev = g_hT[(t - 1) & 1];             // t=0 -> g_hT[1] = feat^T
    const float* hin    = (t == 0) ? feat : g_h[(t - 1) & 1];
    float*       hout   = g_h[t & 1];
    float*       hTout  = g_hT[t & 1];

    const int tid = threadIdx.x;
    const int m0 = blockIdx.x * 64, n0t = blockIdx.y * 32;
    const int nt = blockIdx.y;
    const int ty = tid >> 4, tx = tid & 15;              // m = ty*4+i, n = n0t + tx*2 (+pair)

    // Staging indices
    const int k_a = tid >> 4, mq = tid & 15;             // A: row k_a, 4 m's
    const int gB = tid >> 7, remB = tid & 127;
    const int k_b = remB >> 3, nq = remB & 7;            // B: gate gB, row k_b, 4 n's
    const bool has2 = (tid < 128);
    const int g2 = gB + 2;                               // second B gate slice (tid<128)

    const float* pa  = hTprev + (size_t)k_a * BB + m0 + mq * 4;
    const float* pb  = g_whhT + (size_t)k_b * G3 + gB * DD + n0t + nq * 4;
    const float* pb2 = g_whhT + (size_t)k_b * G3 + g2 * DD + n0t + nq * 4;

    unsigned long long acc[3][4];
    #pragma unroll
    for (int g = 0; g < 3; g++)
        #pragma unroll
        for (int i = 0; i < 4; i++) acc[g][i] = 0ull;

    float4 av, bv, bv2;
    bv2 = make_float4(0.f, 0.f, 0.f, 0.f);

    #define STORE_PANEL(s)                                                        \
        do {                                                                      \
            *(float4*)&As[s][k_a][mq * 4]     = make_float4(av.x, av.x, av.y, av.y); \
            *(float4*)&As[s][k_a][mq * 4 + 2] = make_float4(av.z, av.z, av.w, av.w); \
            *(float4*)&Bs[s][gB][k_b][nq * 4] = bv;                               \
            if (has2) *(float4*)&Bs[s][g2][k_b][nq * 4] = bv2;                    \
        } while (0)

    // Prologue: panel 0 -> buf 0; panel 1 into regs.
    av = *(const float4*)(pa);
    bv = *(const float4*)(pb);
    if (has2) bv2 = *(const float4*)(pb2);
    STORE_PANEL(0);
    av = *(const float4*)(pa + 16 * BB);
    bv = *(const float4*)(pb + 16 * G3);
    if (has2) bv2 = *(const float4*)(pb2 + 16 * G3);
    __syncthreads();

    for (int p = 0; p < 32; p++) {
        const int s = p & 1;
        if (p < 31) {
            const int sn = s ^ 1;
            STORE_PANEL(sn);
        }
        if (p < 30) {
            const size_t offA = (size_t)(p + 2) * 16 * BB;
            const size_t offB = (size_t)(p + 2) * 16 * G3;
            av = *(const float4*)(pa + offA);
            bv = *(const float4*)(pb + offB);
            if (has2) bv2 = *(const float4*)(pb2 + offB);
        }
        #pragma unroll
        for (int k = 0; k < 16; k++) {
            ulonglong2 a01 = *(const ulonglong2*)&As[s][k][ty * 4];
            ulonglong2 a23 = *(const ulonglong2*)&As[s][k][ty * 4 + 2];
            unsigned long long br = *(const unsigned long long*)&Bs[s][0][k][tx * 2];
            unsigned long long bz = *(const unsigned long long*)&Bs[s][1][k][tx * 2];
            unsigned long long bn = *(const unsigned long long*)&Bs[s][2][k][tx * 2];
            unsigned long long a[4] = {a01.x, a01.y, a23.x, a23.y};
            #pragma unroll
            for (int i = 0; i < 4; i++) {
                FMA2(acc[0][i], a[i], br);
                FMA2(acc[1][i], a[i], bz);
                FMA2(acc[2][i], a[i], bn);
            }
        }
        __syncthreads();
    }
    #undef STORE_PANEL

    // Gate epilogue: gi from table (b_ih + b_hh r/z folded in), b_hh_n added here.
    // Writes h_new to global [m][k] and to Hs (smem) for proj + h_T.
    {
        const float2 bhn2 = *(const float2*)&bhh[2 * DD + n0t + tx * 2];
        #pragma unroll
        for (int i = 0; i < 4; i++) {
            int m = m0 + ty * 4 + i;
            int tok = g_tok[m];
            const float* tab = g_tab + (size_t)tok * G3 + n0t + tx * 2;
            float2 gir  = *(const float2*)(tab);
            float2 giz  = *(const float2*)(tab + DD);
            float2 gin  = *(const float2*)(tab + 2 * DD);
            float2 hold = *(const float2*)&hin[(size_t)m * DD + n0t + tx * 2];

            float gr0 = lo32(acc[0][i]), gr1 = hi32(acc[0][i]);
            float gz0 = lo32(acc[1][i]), gz1 = hi32(acc[1][i]);
            float gn0 = lo32(acc[2][i]), gn1 = hi32(acc[2][i]);

            float r0 = sigm(gir.x + gr0);
            float z0 = sigm(giz.x + gz0);
            float nn0 = tanhf(gin.x + r0 * (gn0 + bhn2.x));
            float o0 = (1.f - z0) * nn0 + z0 * hold.x;

            float r1 = sigm(gir.y + gr1);
            float z1 = sigm(giz.y + gz1);
            float nn1 = tanhf(gin.y + r1 * (gn1 + bhn2.y));
            float o1 = (1.f - z1) * nn1 + z1 * hold.y;

            Hs[(ty * 4 + i) * 36 + tx * 2]     = o0;
            Hs[(ty * 4 + i) * 36 + tx * 2 + 1] = o1;
            *(float2*)&hout[(size_t)m * DD + n0t + tx * 2] = make_float2(o0, o1);
        }
    }
    __syncthreads();

    // Projection partial: P[m][c] = sum_{k=0..31} Hs[m][k] * WpT[n0t+k][c]
    // Warp w owns rows w*8..w*8+7, processed in 2 passes of 4 (register cap).
    {
        const int w = tid >> 5, lane = tid & 31;
        #pragma unroll
        for (int pass = 0; pass < 2; pass++) {
            float4 pacc[4];
            #pragma unroll
            for (int rr = 0; rr < 4; rr++) pacc[rr] = make_float4(0.f, 0.f, 0.f, 0.f);
            #pragma unroll
            for (int kq = 0; kq < 8; kq++) {
                const float* wr = g_wpt + (size_t)(n0t + kq * 4) * CC + lane * 4;
                float4 w0 = *(const float4*)(wr);
                float4 w1 = *(const float4*)(wr + CC);
                float4 w2 = *(const float4*)(wr + 2 * CC);
                float4 w3 = *(const float4*)(wr + 3 * CC);
                #pragma unroll
                for (int rr = 0; rr < 4; rr++) {
                    float4 a4 = *(const float4*)&Hs[(w * 8 + pass * 4 + rr) * 36 + kq * 4];
                    pacc[rr].x += a4.x * w0.x; pacc[rr].y += a4.x * w0.y;
                    pacc[rr].z += a4.x * w0.z; pacc[rr].w += a4.x * w0.w;
                    pacc[rr].x += a4.y * w1.x; pacc[rr].y += a4.y * w1.y;
                    pacc[rr].z += a4.y * w1.z; pacc[rr].w += a4.y * w1.w;
                    pacc[rr].x += a4.z * w2.x; pacc[rr].y += a4.z * w2.y;
                    pacc[rr].z += a4.z * w2.z; pacc[rr].w += a4.z * w2.w;
                    pacc[rr].x += a4.w * w3.x; pacc[rr].y += a4.w * w3.y;
                    pacc[rr].z += a4.w * w3.z; pacc[rr].w += a4.w * w3.w;
                }
            }
            #pragma unroll
            for (int rr = 0; rr < 4; rr++) {
                int b = m0 + w * 8 + pass * 4 + rr;
                *(float4*)&g_part[((size_t)nt * BB + b) * CC + lane * 4] = pacc[rr];
            }
        }
    }

    // h_T writeback for next step's A staging: hT[n][m] from Hs.
    {
        const int r = tid & 31, mq8 = tid >> 5;  // r: k-local 0..31, mq8: m-octet 0..7
        float v[8];
        #pragma unroll
        for (int q = 0; q < 8; q++)
            v[q] = Hs[(mq8 * 8 + q) * 36 + r];
        float* dst = hTout + (size_t)(n0t + r) * BB + m0 + mq8 * 8;
        *(float4*)(dst)     = make_float4(v[0], v[1], v[2], v[3]);
        *(float4*)(dst + 4) = make_float4(v[4], v[5], v[6], v[7]);
    }
}

// ---------------------------------------------------------------------------
// Kernel 2 (per step): reduce 16 projection partials + bias -> logits;
// stage logits [B,T,C]; argmax (first-max) -> g_tok and tokens [B,T].
// grid 256 CTAs x 256 threads; one warp per batch row.
// ---------------------------------------------------------------------------
__global__ __launch_bounds__(256)
void finalize(const float* __restrict__ bp, float* __restrict__ out, int t) {
    const int tid = threadIdx.x;
    const int w = tid >> 5, lane = tid & 31;
    const int b = blockIdx.x * 8 + w;

    float4 s = make_float4(0.f, 0.f, 0.f, 0.f);
    #pragma unroll
    for (int p = 0; p < 16; p++) {
        float4 v = *(const float4*)&g_part[((size_t)p * BB + b) * CC + lane * 4];
        s.x += v.x; s.y += v.y; s.z += v.z; s.w += v.w;
    }
    const float4 bpv = *(const float4*)&bp[lane * 4];
    s.x += bpv.x; s.y += bpv.y; s.z += bpv.z; s.w += bpv.w;

    *(float4*)&g_log[((size_t)b * TT + t) * CC + lane * 4] = s;

    // argmax, first-max semantics
    float vv[4] = {s.x, s.y, s.z, s.w};
    float bv = -3.402823466e38f;
    int bi = 0;
    #pragma unroll
    for (int j = 0; j < 4; j++) {
        if (vv[j] > bv) { bv = vv[j]; bi = lane * 4 + j; }
    }
    #pragma unroll
    for (int off = 16; off; off >>= 1) {
        float ov = __shfl_xor_sync(0xffffffffu, bv, off);
        int   oi = __shfl_xor_sync(0xffffffffu, bi, off);
        if (ov > bv || (ov == bv && oi < bi)) { bv = ov; bi = oi; }
    }
    if (lane == 0) {
        g_tok[b] = bi;
        float* out_tok = out + (size_t)BB * CC * TT;
        out_tok[(size_t)b * TT + t] = (float)bi;
    }
}

// ---------------------------------------------------------------------------
// Kernel 3 (once, at end): transpose staged logits [B,T,C] -> d_out [B,C,T].
// ---------------------------------------------------------------------------
__global__ __launch_bounds__(256)
void transp(float* __restrict__ out) {
    __shared__ float tile[32][33];
    const int b  = blockIdx.z;
    const int t0 = blockIdx.x * 32, c0 = blockIdx.y * 32;
    const int tx = threadIdx.x, ty = threadIdx.y;

    #pragma unroll
    for (int i = ty; i < 32; i += 8) {
        int t = t0 + i;
        if (t < TT)
            tile[i][tx] = g_log[((size_t)b * TT + t) * CC + c0 + tx];
    }
    __syncthreads();
    #pragma unroll
    for (int i = ty; i < 32; i += 8) {
        int c = c0 + i;
        int t = t0 + tx;
        if (t < TT)
            out[((size_t)b * CC + c) * TT + t] = tile[tx][i];
    }
}

// ---------------------------------------------------------------------------
// kernel_launch: graph-capturable, no allocation.
// Inputs (metadata order): feat, W_ih, W_hh, b_ih, b_hh, W_proj, b_proj, embed
// Output: logits [B,C,T] float32 then tokens [B,T] as float32.
// ---------------------------------------------------------------------------
extern "C" void kernel_launch(void* const* d_in, const int* in_sizes, int n_in,
                              void* d_out, int out_size) {
    const float* feat  = (const float*)d_in[0];
    const float* Wih   = (const float*)d_in[1];
    const float* Whh   = (const float*)d_in[2];
    const float* bih   = (const float*)d_in[3];
    const float* bhh   = (const float*)d_in[4];
    const float* Wp    = (const float*)d_in[5];
    const float* bp    = (const float*)d_in[6];
    const float* embed = (const float*)d_in[7];
    float* out = (float*)d_out;

    build_tab<<<dim3(CC + 1, G3 / 256), 256>>>(Wih, bih, bhh, embed);
    build_wpt<<<DD * CC / 256, 256>>>(Wp);
    build_whhT<<<DD * G3 / 256, 256>>>(Whh);
    build_featT<<<DD * BB / 256, 256>>>(feat);
    init_tok<<<(BB + 255) / 256, 256>>>();

    for (int t = 0; t < TT; t++) {
        step_h<<<dim3(BB / 64, DD / 32), 256>>>(feat, bhh, t);
        finalize<<<BB / 8, 256>>>(bp, out, t);
    }

    transp<<<dim3((TT + 31) / 32, CC / 32, BB), dim3(32, 8)>>>(out);
}

// round 13
// speedup vs baseline: 1.4624x; 1.4624x over previous
#include <cuda_runtime.h>
#include <math.h>

// Problem constants
#define BB 2048   // batch
#define DD 512    // hidden
#define CC 128    // vocab
#define TT 151    // steps
#define G3 1536   // 3*DD

// Persistent scratch (allowed: __device__ globals, no runtime allocation)
__device__ float g_h[2][BB * DD];             // ping-pong hidden state, 8 MB
__device__ float g_tab[(CC + 1) * G3];        // gi table: embed@W_ih^T + b_ih (+ b_hh r/z folded)
__device__ int   g_tok[BB];                   // previous token per batch row
__device__ float g_log[(size_t)BB * TT * CC]; // logits staged [B,T,C] (coalesced), 158 MB
__device__ float g_part[8 * BB * CC];         // projection partials [n_tile][B][C], 8 MB
__device__ float g_wpt[DD * CC];              // W_proj transposed [D][C], 256 KB
__device__ int   g_done[32];                  // per-m-block step flag for inline finalize

__device__ __forceinline__ float sigm(float x) { return 1.f / (1.f + expf(-x)); }

// Packed fp32x2 FMA (Blackwell FFMA2; only reachable via PTX fma.rn.f32x2)
#define FMA2(acc, a, b) \
    asm("fma.rn.f32x2 %0, %1, %2, %0;" : "+l"(acc) : "l"(a), "l"(b))

__device__ __forceinline__ float lo32(unsigned long long v) { return __uint_as_float((unsigned)v); }
__device__ __forceinline__ float hi32(unsigned long long v) { return __uint_as_float((unsigned)(v >> 32)); }

// duplicate one fp32 into both lanes of a packed f32x2 (ALU pipe, not LDS)
__device__ __forceinline__ unsigned long long dup2(float x) {
    unsigned long long r;
    asm("mov.b64 %0, {%1, %1};" : "=l"(r) : "f"(x));
    return r;
}

// ---------------------------------------------------------------------------
// Precompute gi table: g_tab[c][j] = embed[c]·W_ih[j] + b_ih[j] + (j<1024 ? b_hh[j] : 0)
// Row CC (=128) is the zero-input row (t=0): just the biases.
// ---------------------------------------------------------------------------
__global__ void build_tab(const float* __restrict__ Wih, const float* __restrict__ bih,
                          const float* __restrict__ bhh, const float* __restrict__ embed) {
    __shared__ float se[DD];
    int c = blockIdx.x;                      // 0..128
    int j = blockIdx.y * 256 + threadIdx.x;  // 0..1535
    for (int i = threadIdx.x; i < DD; i += 256)
        se[i] = (c < CC) ? embed[c * DD + i] : 0.f;
    __syncthreads();
    float acc = bih[j] + (j < 2 * DD ? bhh[j] : 0.f);
    if (c < CC) {
        const float4* w  = (const float4*)(Wih + (size_t)j * DD);
        const float4* s4 = (const float4*)se;
        #pragma unroll 8
        for (int k = 0; k < DD / 4; k++) {
            float4 wv = w[k], sv = s4[k];
            acc += wv.x * sv.x;
            acc += wv.y * sv.y;
            acc += wv.z * sv.z;
            acc += wv.w * sv.w;
        }
    }
    g_tab[(size_t)c * G3 + j] = acc;
}

// W_proj^T: g_wpt[n][c] = Wp[c][n]  (one-time, coalesced writes)
__global__ void build_wpt(const float* __restrict__ Wp) {
    int i = blockIdx.x * 256 + threadIdx.x;  // 0 .. 512*128-1
    int n = i >> 7, c = i & 127;
    g_wpt[n * CC + c] = Wp[(size_t)c * DD + n];
}

__global__ void init_tok() {
    int i = blockIdx.x * blockDim.x + threadIdx.x;
    if (i < BB) g_tok[i] = CC;  // zero-input table row
    if (i < 32) g_done[i] = 0;  // reset inline-finalize flags (every graph replay)
}

// ---------------------------------------------------------------------------
// Kernel 1: (a) CTAs with blockIdx.y==0 first finalize step t-1 for their own
//           64 batch rows (reduce 8 projection partials + bias -> logits
//           staged [B,T,C], argmax -> g_tok, token output), then set flag.
//           (b) gh = h @ W_hh^T (FFMA2 GEMM, bitwise-identical to R10),
//           fused gates + gi table lookup -> h_new (consumers poll the flag
//           only at epilogue time, ~75us after it was set -> zero wait),
//           plus this CTA's 64-col partial of the projection h_new @ Wp^T.
// grid (BB/64, DD/64) = (32, 8) = 256 CTAs, 256 threads, occ 2 (all resident).
// ---------------------------------------------------------------------------
__global__ __launch_bounds__(256, 2)
void step_h(const float* __restrict__ feat, const float* __restrict__ Whh,
            const float* __restrict__ bhh, const float* __restrict__ bp,
            float* __restrict__ out, int t) {
    // Raw smem carved into phase-disjoint views:
    //   GEMM phase: As[2][16][68] float (8704 B) + Bs[2][3][16][68] float (26112 B)
    //   Proj phase: Hs[64][68] float (17408 B), overlapping As + head of Bs
    __shared__ __align__(16) unsigned char sraw[34816];
    float (*As)[16][68]    = (float(*)[16][68])sraw;
    float (*Bs)[3][16][68] = (float(*)[3][16][68])(sraw + 8704);
    float* Hs = (float*)sraw;  // stride 68

    const float* hin  = (t == 0) ? feat : g_h[(t - 1) & 1];
    float*       hout = g_h[t & 1];

    const int tid = threadIdx.x;
    const int m0 = blockIdx.x * 64, n0 = blockIdx.y * 64;
    const int ty = tid >> 4, tx = tid & 15;  // compute tile: m = ty*4+i, n = tx*4+j
    const int sm = tid >> 2, skq = tid & 3;  // staging: row = tid/4, k-quad = tid%4

    // ---- Inline finalize of step t-1 (producer CTAs only) -----------------
    if (t > 0 && blockIdx.y == 0) {
        const int w = tid >> 5, lane = tid & 31;
        float* out_tok = out + (size_t)BB * CC * TT;
        const float4 bpv = *(const float4*)&bp[lane * 4];
        #pragma unroll
        for (int rr = 0; rr < 8; rr++) {
            const int b = m0 + w * 8 + rr;
            float4 s = make_float4(0.f, 0.f, 0.f, 0.f);
            #pragma unroll
            for (int p = 0; p < 8; p++) {
                float4 v = *(const float4*)&g_part[((size_t)p * BB + b) * CC + lane * 4];
                s.x += v.x; s.y += v.y; s.z += v.z; s.w += v.w;
            }
            s.x += bpv.x; s.y += bpv.y; s.z += bpv.z; s.w += bpv.w;

            *(float4*)&g_log[((size_t)b * TT + (t - 1)) * CC + lane * 4] = s;

            // argmax, first-max semantics
            float vv[4] = {s.x, s.y, s.z, s.w};
            float bv = -3.402823466e38f;
            int bi = 0;
            #pragma unroll
            for (int j = 0; j < 4; j++) {
                if (vv[j] > bv) { bv = vv[j]; bi = lane * 4 + j; }
            }
            #pragma unroll
            for (int off = 16; off; off >>= 1) {
                float ov = __shfl_xor_sync(0xffffffffu, bv, off);
                int   oi = __shfl_xor_sync(0xffffffffu, bi, off);
                if (ov > bv || (ov == bv && oi < bi)) { bv = ov; bi = oi; }
            }
            if (lane == 0) {
                g_tok[b] = bi;
                out_tok[(size_t)b * TT + (t - 1)] = (float)bi;
            }
        }
        __threadfence();
        __syncthreads();
        if (tid == 0) atomicExch(&g_done[blockIdx.x], t);
    }

    // ---- gh GEMM (bitwise-identical accumulation to R10) ------------------
    const float* pa  = hin + (size_t)(m0 + sm) * DD + skq * 4;
    const float* pb0 = Whh + (size_t)(n0 + sm) * DD + skq * 4;
    const float* pb1 = pb0 + (size_t)DD * DD;
    const float* pb2 = pb1 + (size_t)DD * DD;

    unsigned long long acc[3][4][2];
    #pragma unroll
    for (int g = 0; g < 3; g++)
        #pragma unroll
        for (int i = 0; i < 4; i++) { acc[g][i][0] = 0ull; acc[g][i][1] = 0ull; }

    float4 av, bv0, bv1, bv2;

    #define STORE_PANEL(s)                                                    \
        do {                                                                  \
            As[s][skq * 4 + 0][sm] = av.x;                                    \
            As[s][skq * 4 + 1][sm] = av.y;                                    \
            As[s][skq * 4 + 2][sm] = av.z;                                    \
            As[s][skq * 4 + 3][sm] = av.w;                                    \
            Bs[s][0][skq * 4 + 0][sm] = bv0.x; Bs[s][0][skq * 4 + 1][sm] = bv0.y; \
            Bs[s][0][skq * 4 + 2][sm] = bv0.z; Bs[s][0][skq * 4 + 3][sm] = bv0.w; \
            Bs[s][1][skq * 4 + 0][sm] = bv1.x; Bs[s][1][skq * 4 + 1][sm] = bv1.y; \
            Bs[s][1][skq * 4 + 2][sm] = bv1.z; Bs[s][1][skq * 4 + 3][sm] = bv1.w; \
            Bs[s][2][skq * 4 + 0][sm] = bv2.x; Bs[s][2][skq * 4 + 1][sm] = bv2.y; \
            Bs[s][2][skq * 4 + 2][sm] = bv2.z; Bs[s][2][skq * 4 + 3][sm] = bv2.w; \
        } while (0)

    // Prologue: panel 0 -> buf 0; panel 1 into regs.
    av  = *(const float4*)(pa);
    bv0 = *(const float4*)(pb0);
    bv1 = *(const float4*)(pb1);
    bv2 = *(const float4*)(pb2);
    STORE_PANEL(0);
    av  = *(const float4*)(pa  + 16);
    bv0 = *(const float4*)(pb0 + 16);
    bv1 = *(const float4*)(pb1 + 16);
    bv2 = *(const float4*)(pb2 + 16);
    __syncthreads();

    for (int p = 0; p < 32; p++) {
        const int s = p & 1;
        if (p < 31)
            STORE_PANEL(s ^ 1);
        if (p < 30) {
            const int kk = (p + 2) * 16;
            av  = *(const float4*)(pa  + kk);
            bv0 = *(const float4*)(pb0 + kk);
            bv1 = *(const float4*)(pb1 + kk);
            bv2 = *(const float4*)(pb2 + kk);
        }
        #pragma unroll
        for (int k = 0; k < 16; k++) {
            float4 a4 = *(const float4*)&As[s][k][ty * 4];
            ulonglong2 br = *(const ulonglong2*)&Bs[s][0][k][tx * 4];
            ulonglong2 bz = *(const ulonglong2*)&Bs[s][1][k][tx * 4];
            ulonglong2 bn = *(const ulonglong2*)&Bs[s][2][k][tx * 4];
            unsigned long long a[4] = {dup2(a4.x), dup2(a4.y), dup2(a4.z), dup2(a4.w)};
            #pragma unroll
            for (int i = 0; i < 4; i++) {
                FMA2(acc[0][i][0], a[i], br.x); FMA2(acc[0][i][1], a[i], br.y);
                FMA2(acc[1][i][0], a[i], bz.x); FMA2(acc[1][i][1], a[i], bz.y);
                FMA2(acc[2][i][0], a[i], bn.x); FMA2(acc[2][i][1], a[i], bn.y);
            }
        }
        __syncthreads();
    }
    #undef STORE_PANEL

    // ---- Wait for this m-block's tokens (set ~75us ago by the y==0 CTA) ---
    if (t > 0) {
        if (tid == 0) {
            while (((volatile int*)g_done)[blockIdx.x] < t) { }
        }
        __syncthreads();
        __threadfence();  // acquire: order g_tok reads after flag observation
    }

    // Gate epilogue: gi from table (b_ih + b_hh r/z folded in), b_hh_n added here.
    // Write h_new to global AND to Hs (smem) for the fused projection partial.
    const float4 bhn4 = *(const float4*)&bhh[2 * DD + n0 + tx * 4];
    #pragma unroll
    for (int i = 0; i < 4; i++) {
        int m = m0 + ty * 4 + i;
        int tok = g_tok[m];
        const float* tab = g_tab + (size_t)tok * G3 + n0 + tx * 4;
        float4 gir  = *(const float4*)(tab);
        float4 giz  = *(const float4*)(tab + DD);
        float4 gin  = *(const float4*)(tab + 2 * DD);
        float4 hold = *(const float4*)&hin[(size_t)m * DD + n0 + tx * 4];

        float gr[4], gz[4], gn[4];
        gr[0] = lo32(acc[0][i][0]); gr[1] = hi32(acc[0][i][0]);
        gr[2] = lo32(acc[0][i][1]); gr[3] = hi32(acc[0][i][1]);
        gz[0] = lo32(acc[1][i][0]); gz[1] = hi32(acc[1][i][0]);
        gz[2] = lo32(acc[1][i][1]); gz[3] = hi32(acc[1][i][1]);
        gn[0] = lo32(acc[2][i][0]); gn[1] = hi32(acc[2][i][0]);
        gn[2] = lo32(acc[2][i][1]); gn[3] = hi32(acc[2][i][1]);

        float ir[4] = {gir.x, gir.y, gir.z, gir.w};
        float iz[4] = {giz.x, giz.y, giz.z, giz.w};
        float in_[4] = {gin.x, gin.y, gin.z, gin.w};
        float bn_[4] = {bhn4.x, bhn4.y, bhn4.z, bhn4.w};
        float ho[4] = {hold.x, hold.y, hold.z, hold.w};
        float o[4];
        #pragma unroll
        for (int j = 0; j < 4; j++) {
            float r = sigm(ir[j] + gr[j]);
            float z = sigm(iz[j] + gz[j]);
            float n = tanhf(in_[j] + r * (gn[j] + bn_[j]));
            o[j] = (1.f - z) * n + z * ho[j];
            Hs[(ty * 4 + i) * 68 + tx * 4 + j] = o[j];
        }
        *(float4*)&hout[(size_t)m * DD + n0 + tx * 4] =
            make_float4(o[0], o[1], o[2], o[3]);
    }
    __syncthreads();

    // Projection partial: P[m][c] = sum_{k=0..63} Hs[m][k] * WpT[n0+k][c]
    // Warp w owns rows w*8..w*8+7; lane owns 4 classes (c = lane*4..+3).
    {
        const int w = tid >> 5, lane = tid & 31;
        float4 pacc[8];
        #pragma unroll
        for (int rr = 0; rr < 8; rr++) pacc[rr] = make_float4(0.f, 0.f, 0.f, 0.f);

        #pragma unroll 4
        for (int kq = 0; kq < 16; kq++) {
            const float* wr = g_wpt + (size_t)(n0 + kq * 4) * CC + lane * 4;
            float4 w0 = *(const float4*)(wr);
            float4 w1 = *(const float4*)(wr + CC);
            float4 w2 = *(const float4*)(wr + 2 * CC);
            float4 w3 = *(const float4*)(wr + 3 * CC);
            #pragma unroll
            for (int rr = 0; rr < 8; rr++) {
                float4 a4 = *(const float4*)&Hs[(w * 8 + rr) * 68 + kq * 4];
                pacc[rr].x += a4.x * w0.x; pacc[rr].y += a4.x * w0.y;
                pacc[rr].z += a4.x * w0.z; pacc[rr].w += a4.x * w0.w;
                pacc[rr].x += a4.y * w1.x; pacc[rr].y += a4.y * w1.y;
                pacc[rr].z += a4.y * w1.z; pacc[rr].w += a4.y * w1.w;
                pacc[rr].x += a4.z * w2.x; pacc[rr].y += a4.z * w2.y;
                pacc[rr].z += a4.z * w2.z; pacc[rr].w += a4.z * w2.w;
                pacc[rr].x += a4.w * w3.x; pacc[rr].y += a4.w * w3.y;
                pacc[rr].z += a4.w * w3.z; pacc[rr].w += a4.w * w3.w;
            }
        }
        const int nt = blockIdx.y;
        #pragma unroll
        for (int rr = 0; rr < 8; rr++) {
            int b = m0 + w * 8 + rr;
            *(float4*)&g_part[((size_t)nt * BB + b) * CC + lane * 4] = pacc[rr];
        }
    }
}

// ---------------------------------------------------------------------------
// Kernel 2 (once, after the loop): finalize step TT-1.
// grid 256 CTAs x 256 threads; one warp per batch row.
// ---------------------------------------------------------------------------
__global__ __launch_bounds__(256)
void finalize(const float* __restrict__ bp, float* __restrict__ out, int t) {
    const int tid = threadIdx.x;
    const int w = tid >> 5, lane = tid & 31;
    const int b = blockIdx.x * 8 + w;

    float4 s = make_float4(0.f, 0.f, 0.f, 0.f);
    #pragma unroll
    for (int p = 0; p < 8; p++) {
        float4 v = *(const float4*)&g_part[((size_t)p * BB + b) * CC + lane * 4];
        s.x += v.x; s.y += v.y; s.z += v.z; s.w += v.w;
    }
    const float4 bpv = *(const float4*)&bp[lane * 4];
    s.x += bpv.x; s.y += bpv.y; s.z += bpv.z; s.w += bpv.w;

    *(float4*)&g_log[((size_t)b * TT + t) * CC + lane * 4] = s;

    // argmax, first-max semantics
    float vv[4] = {s.x, s.y, s.z, s.w};
    float bv = -3.402823466e38f;
    int bi = 0;
    #pragma unroll
    for (int j = 0; j < 4; j++) {
        if (vv[j] > bv) { bv = vv[j]; bi = lane * 4 + j; }
    }
    #pragma unroll
    for (int off = 16; off; off >>= 1) {
        float ov = __shfl_xor_sync(0xffffffffu, bv, off);
        int   oi = __shfl_xor_sync(0xffffffffu, bi, off);
        if (ov > bv || (ov == bv && oi < bi)) { bv = ov; bi = oi; }
    }
    if (lane == 0) {
        g_tok[b] = bi;
        float* out_tok = out + (size_t)BB * CC * TT;
        out_tok[(size_t)b * TT + t] = (float)bi;
    }
}

// ---------------------------------------------------------------------------
// Kernel 3 (once, at end): transpose staged logits [B,T,C] -> d_out [B,C,T].
// ---------------------------------------------------------------------------
__global__ __launch_bounds__(256)
void transp(float* __restrict__ out) {
    __shared__ float tile[32][33];
    const int b  = blockIdx.z;
    const int t0 = blockIdx.x * 32, c0 = blockIdx.y * 32;
    const int tx = threadIdx.x, ty = threadIdx.y;

    #pragma unroll
    for (int i = ty; i < 32; i += 8) {
        int t = t0 + i;
        if (t < TT)
            tile[i][tx] = g_log[((size_t)b * TT + t) * CC + c0 + tx];
    }
    __syncthreads();
    #pragma unroll
    for (int i = ty; i < 32; i += 8) {
        int c = c0 + i;
        int t = t0 + tx;
        if (t < TT)
            out[((size_t)b * CC + c) * TT + t] = tile[tx][i];
    }
}

// ---------------------------------------------------------------------------
// kernel_launch: graph-capturable, no allocation.
// Inputs (metadata order): feat, W_ih, W_hh, b_ih, b_hh, W_proj, b_proj, embed
// Output: logits [B,C,T] float32 then tokens [B,T] as float32.
// ---------------------------------------------------------------------------
extern "C" void kernel_launch(void* const* d_in, const int* in_sizes, int n_in,
                              void* d_out, int out_size) {
    const float* feat  = (const float*)d_in[0];
    const float* Wih   = (const float*)d_in[1];
    const float* Whh   = (const float*)d_in[2];
    const float* bih   = (const float*)d_in[3];
    const float* bhh   = (const float*)d_in[4];
    const float* Wp    = (const float*)d_in[5];
    const float* bp    = (const float*)d_in[6];
    const float* embed = (const float*)d_in[7];
    float* out = (float*)d_out;

    build_tab<<<dim3(CC + 1, G3 / 256), 256>>>(Wih, bih, bhh, embed);
    build_wpt<<<DD * CC / 256, 256>>>(Wp);
    init_tok<<<(BB + 255) / 256, 256>>>();

    for (int t = 0; t < TT; t++) {
        step_h<<<dim3(BB / 64, DD / 64), 256>>>(feat, Whh, bhh, bp, out, t);
    }
    finalize<<<BB / 8, 256>>>(bp, out, TT - 1);

    transp<<<dim3((TT + 31) / 32, CC / 32, BB), dim3(32, 8)>>>(out);
}